// round 15
// baseline (speedup 1.0000x reference)
#include <cuda_runtime.h>
#include <cuda_fp16.h>
#include <math.h>

// ---------------- problem constants ----------------
#define BSZ 2
#define SEQ 16384
#define DM  512
#define DKD 256
#define DVD 512
#define NH  4
#define HKD 64
#define HVD 128
#define CHK 64
#define NCK (SEQ/CHK)
#define TT  (BSZ*SEQ)
#define GLR 16
#define NQKVG 1536       // packed [q|k|v|g] output width

#define QOFF(row,h,j) ((size_t)(row)*NQKVG + (size_t)(h)*64 + (j))
#define KOFF(row,h,j) ((size_t)(row)*NQKVG + 256 + (size_t)(h)*64 + (j))
#define VOFF(row,h,j) ((size_t)(row)*NQKVG + 512 + (size_t)(h)*128 + (j))
#define GOFF(row,h,j) ((size_t)(row)*NQKVG + 1024 + (size_t)(h)*128 + (j))

// ---------------- device scratch ----------------
__device__ float   g_qkvg[(size_t)TT*NQKVG];
__device__ float   g_gkl [(size_t)TT*GLR];
__device__ __half  g_P   [(size_t)BSZ*NH*NCK*HKD*HVD];   // fp16 chunk kv summaries
__device__ float   g_dec [(size_t)BSZ*NH*NCK*HKD];
__device__ __half  g_hs  [(size_t)BSZ*NH*NCK*HKD*HVD];   // fp16 chunk-start states
__device__ __half  g_xh  [(size_t)TT*DM];
__device__ __half  g_xl  [(size_t)TT*DM];
__device__ __half  g_yh  [(size_t)TT*DVD];
__device__ __half  g_yl  [(size_t)TT*DVD];
__device__ __half  g_wh  [(size_t)DM*NQKVG];   // [K,N] packed [Wq|Wk|Wv|Wg], fp16
__device__ __half  g_woh [(size_t)DVD*DM];     // [K,N], fp16

// ---------------- helpers ----------------
__device__ __forceinline__ void split2h(float v, unsigned short& h, unsigned short& l)
{
    __half hb = __float2half(v);
    float lo = v - __half2float(hb);
    h = __half_as_ushort(hb);
    l = __half_as_ushort(__float2half(lo));
}

// packed f32x2 FMA (Blackwell): d += a*b elementwise on 2 packed floats
__device__ __forceinline__ void fma2(unsigned long long& d,
                                     unsigned long long a, unsigned long long b)
{
    asm("fma.rn.f32x2 %0, %1, %2, %0;" : "+l"(d) : "l"(a), "l"(b));
}
__device__ __forceinline__ unsigned long long packdup(float v)
{
    unsigned long long r;
    asm("mov.b64 %0, {%1, %1};" : "=l"(r) : "f"(v));
    return r;
}
__device__ __forceinline__ float2 unpack2(unsigned long long v)
{
    float lo, hi;
    asm("mov.b64 {%0, %1}, %2;" : "=f"(lo), "=f"(hi) : "l"(v));
    return make_float2(lo, hi);
}

// ---------------- split x (fp16 hi/lo) + gkl = x @ Wgk1 ----------------
__global__ void split_gkl(const float* __restrict__ x, const float* __restrict__ W)
{
    __shared__ float w[DM * GLR];
    int tid = threadIdx.x;
    for (int i = tid; i < DM * GLR; i += 256) w[i] = W[i];
    __syncthreads();

    int row = blockIdx.x * 64 + (tid >> 2);
    int q = (tid & 3) * 4;
    float a0 = 0.f, a1 = 0.f, a2 = 0.f, a3 = 0.f;
    const float4* xr = (const float4*)(x + (size_t)row * DM);
#pragma unroll 4
    for (int k4 = 0; k4 < DM / 4; k4++) {
        float4 v = xr[k4];
        const float* wb = &w[k4 * 4 * GLR + q];
        a0 += v.x * wb[0] + v.y * wb[GLR] + v.z * wb[2 * GLR] + v.w * wb[3 * GLR];
        a1 += v.x * wb[1] + v.y * wb[GLR + 1] + v.z * wb[2 * GLR + 1] + v.w * wb[3 * GLR + 1];
        a2 += v.x * wb[2] + v.y * wb[GLR + 2] + v.z * wb[2 * GLR + 2] + v.w * wb[3 * GLR + 2];
        a3 += v.x * wb[3] + v.y * wb[GLR + 3] + v.z * wb[2 * GLR + 3] + v.w * wb[3 * GLR + 3];
    }
    *(float4*)&g_gkl[(size_t)row * GLR + q] = make_float4(a0, a1, a2, a3);

    size_t base = (size_t)blockIdx.x * 64 * (DM / 4);
    const float4* x4 = (const float4*)x;
    for (int i = tid; i < 64 * DM / 4; i += 256) {
        float4 v = x4[base + i];
        ushort4 h, l;
        split2h(v.x, h.x, l.x); split2h(v.y, h.y, l.y);
        split2h(v.z, h.z, l.z); split2h(v.w, h.w, l.w);
        *(ushort4*)&g_xh[(base + i) * 4] = h;
        *(ushort4*)&g_xl[(base + i) * 4] = l;
    }
}

// ---------------- pack weights to fp16 ([K,N] layout for mma.sync B) ----------
__global__ void split_w(const float* __restrict__ Wq, const float* __restrict__ Wk,
                        const float* __restrict__ Wv, const float* __restrict__ Wg,
                        const float* __restrict__ Wo)
{
    int idx = blockIdx.x * 256 + threadIdx.x;
    if (idx < DM * NQKVG) {
        int row = idx / NQKVG, col = idx % NQKVG;
        float v;
        if      (col < 256)  v = Wq[row * DKD + col];
        else if (col < 512)  v = Wk[row * DKD + col - 256];
        else if (col < 1024) v = Wv[row * DVD + col - 512];
        else                 v = Wg[row * DVD + col - 1024];
        g_wh[idx] = __float2half(v);
    } else {
        int j = idx - DM * NQKVG;
        if (j < DVD * DM) g_woh[j] = __float2half(Wo[j]);
    }
}

// ---------------- fp16x2 tensor-core GEMM: C = (Ah+Al) @ Bh -------------------
// 128x128 tile, BK=32, 256 threads, 2-stage. (Known ceiling ~340 TF/s.)
#define GSTG 2
#define SA_STRIDE 40
#define SB_STRIDE 136
#define SA_SZ (128 * SA_STRIDE)              // shorts
#define SB_SZ (32 * SB_STRIDE)               // shorts
#define STG_SHORTS (2 * SA_SZ + SB_SZ)       // Ah | Al | Bh
#define GEMM_SMEM (GSTG * STG_SHORTS * 2)    // bytes = 58368

__global__ __launch_bounds__(256, 2) void gemm_f16x2(
    const __half* __restrict__ Ah, const __half* __restrict__ Al,
    const __half* __restrict__ Bh,
    float* __restrict__ C, int M, int N, int K, int qcols)
{
    extern __shared__ __align__(16) unsigned short smem_u[];

    int tid = threadIdx.x;
    int bm = blockIdx.y * 128, bn = blockIdx.x * 128;
    int warp = tid >> 5, lane = tid & 31;
    int wm = (warp & 1) * 64, wn = (warp >> 1) * 32;

    float c[4][4][4];
#pragma unroll
    for (int a = 0; a < 4; a++)
#pragma unroll
        for (int b = 0; b < 4; b++)
#pragma unroll
            for (int d = 0; d < 4; d++) c[a][b][d] = 0.f;

    int nk = K / 32;

    int arow[2], acol[2], brow[2], bcol[2];
#pragma unroll
    for (int i = 0; i < 2; i++) {
        int idx = tid * 2 + i;
        arow[i] = idx >> 2; acol[i] = (idx & 3) * 8;
        int idxb = tid + i * 256;
        brow[i] = idxb >> 4; bcol[i] = (idxb & 15) * 8;
    }

#define GEMM_ISSUE(S) do {                                                     \
        int kt_ = (S) * 32;                                                    \
        unsigned short* st_ = smem_u + ((S) & 1) * STG_SHORTS;                 \
        _Pragma("unroll")                                                      \
        for (int i_ = 0; i_ < 2; i_++) {                                       \
            size_t goa_ = (size_t)(bm + arow[i_]) * K + kt_ + acol[i_];        \
            unsigned soa_ = arow[i_] * SA_STRIDE + acol[i_];                   \
            asm volatile("cp.async.cg.shared.global [%0],[%1],16;\n" ::        \
                "r"((unsigned)__cvta_generic_to_shared(st_ + soa_)), "l"(Ah + goa_)); \
            asm volatile("cp.async.cg.shared.global [%0],[%1],16;\n" ::        \
                "r"((unsigned)__cvta_generic_to_shared(st_ + SA_SZ + soa_)), "l"(Al + goa_)); \
            size_t gob_ = (size_t)(kt_ + brow[i_]) * N + bn + bcol[i_];        \
            unsigned sob_ = brow[i_] * SB_STRIDE + bcol[i_];                   \
            asm volatile("cp.async.cg.shared.global [%0],[%1],16;\n" ::        \
                "r"((unsigned)__cvta_generic_to_shared(st_ + 2 * SA_SZ + sob_)), "l"(Bh + gob_)); \
        }                                                                      \
        asm volatile("cp.async.commit_group;\n");                              \
    } while (0)

    GEMM_ISSUE(0);

    for (int s = 0; s < nk; s++) {
        asm volatile("cp.async.wait_group 0;\n");
        __syncthreads();
        if (s + 1 < nk) GEMM_ISSUE(s + 1);

        unsigned short* st = smem_u + (s & 1) * STG_SHORTS;
        unsigned short* pAh = st;
        unsigned short* pAl = st + SA_SZ;
        unsigned short* pBh = st + 2 * SA_SZ;

#pragma unroll
        for (int kc = 0; kc < 2; kc++) {
            unsigned af[4][4], bfh[4][2];
            int acol16 = kc * 16 + (lane >> 4) * 8;
            int arow16 = lane & 15;
#pragma unroll
            for (int mt = 0; mt < 4; mt++) {
                unsigned addr = (unsigned)__cvta_generic_to_shared(
                    &pAh[(wm + mt * 16 + arow16) * SA_STRIDE + acol16]);
                asm volatile("ldmatrix.sync.aligned.m8n8.x4.shared.b16 {%0,%1,%2,%3},[%4];"
                    : "=r"(af[mt][0]), "=r"(af[mt][1]), "=r"(af[mt][2]), "=r"(af[mt][3])
                    : "r"(addr));
            }
            int brow16 = kc * 16 + (lane & 15);
#pragma unroll
            for (int g = 0; g < 2; g++) {
                int colb = wn + g * 16 + (lane >> 4) * 8;
                unsigned r0, r1, r2, r3;
                unsigned addr = (unsigned)__cvta_generic_to_shared(
                    &pBh[brow16 * SB_STRIDE + colb]);
                asm volatile("ldmatrix.sync.aligned.m8n8.x4.trans.shared.b16 {%0,%1,%2,%3},[%4];"
                    : "=r"(r0), "=r"(r1), "=r"(r2), "=r"(r3) : "r"(addr));
                bfh[g * 2][0] = r0; bfh[g * 2][1] = r1;
                bfh[g * 2 + 1][0] = r2; bfh[g * 2 + 1][1] = r3;
            }

#define MMA16(AF, BF)                                                          \
            _Pragma("unroll")                                                  \
            for (int mt = 0; mt < 4; mt++)                                     \
                _Pragma("unroll")                                              \
                for (int nt = 0; nt < 4; nt++)                                 \
                    asm volatile(                                              \
                        "mma.sync.aligned.m16n8k16.row.col.f32.f16.f16.f32 "   \
                        "{%0,%1,%2,%3},{%4,%5,%6,%7},{%8,%9},{%0,%1,%2,%3};"   \
                        : "+f"(c[mt][nt][0]), "+f"(c[mt][nt][1]),              \
                          "+f"(c[mt][nt][2]), "+f"(c[mt][nt][3])               \
                        : "r"(AF[mt][0]), "r"(AF[mt][1]),                      \
                          "r"(AF[mt][2]), "r"(AF[mt][3]),                      \
                          "r"(BF[nt][0]), "r"(BF[nt][1]))

            MMA16(af, bfh);      // Ah @ Bh

#pragma unroll
            for (int mt = 0; mt < 4; mt++) {   // reload A frags with Al
                unsigned addr = (unsigned)__cvta_generic_to_shared(
                    &pAl[(wm + mt * 16 + arow16) * SA_STRIDE + acol16]);
                asm volatile("ldmatrix.sync.aligned.m8n8.x4.shared.b16 {%0,%1,%2,%3},[%4];"
                    : "=r"(af[mt][0]), "=r"(af[mt][1]), "=r"(af[mt][2]), "=r"(af[mt][3])
                    : "r"(addr));
            }
            MMA16(af, bfh);      // Al @ Bh
#undef MMA16
        }
    }
#undef GEMM_ISSUE

#pragma unroll
    for (int mt = 0; mt < 4; mt++)
#pragma unroll
        for (int nt = 0; nt < 4; nt++) {
            int colg = bn + wn + nt * 8 + (lane & 3) * 2;
            float alpha = (colg < qcols) ? 0.125f : 1.0f;
            int row0 = bm + wm + mt * 16 + (lane >> 2);
            *(float2*)&C[(size_t)row0 * N + colg] =
                make_float2(c[mt][nt][0] * alpha, c[mt][nt][1] * alpha);
            *(float2*)&C[(size_t)(row0 + 8) * N + colg] =
                make_float2(c[mt][nt][2] * alpha, c[mt][nt][3] * alpha);
        }
}

// ---------------- per-chunk prep: gate + cumsum + q~, k2, P(fp16), dec --------
__global__ void chunk_prep(const float* __restrict__ Wgk2, const float* __restrict__ bgk2)
{
    __shared__ __align__(16) float slam[CHK][HKD];   // Lam, reused as kd
    __shared__ __align__(16) float sv[CHK][HVD];     // staging then v
    __shared__ float stot[4][HKD];
    __shared__ float selaml[HKD];
    int c = blockIdx.x, h = blockIdx.y, b = blockIdx.z;
    int tid = threadIdx.x;
    int r0 = b * SEQ + c * CHK;
    int cb = h * HKD;

    float* sgkl = &sv[0][0];
    float* sw2  = &sv[0][0] + 1024;
    float* sbp  = &sv[0][0] + 2048;

    for (int e = tid; e < CHK * GLR; e += 256)
        sgkl[e] = g_gkl[(size_t)(r0 + (e >> 4)) * GLR + (e & 15)];
    for (int e = tid; e < GLR * HKD; e += 256)
        sw2[e] = Wgk2[(e >> 6) * DKD + cb + (e & 63)];
    if (tid < HKD) sbp[tid] = bgk2[cb + tid];
    __syncthreads();

    for (int e = tid; e < CHK * HKD; e += 256) {
        int t = e >> 6, j = e & 63;
        float z = sbp[j];
#pragma unroll
        for (int i = 0; i < GLR; i++)
            z += sgkl[t * GLR + i] * sw2[i * HKD + j];
        float ls = (z >= 0.f) ? (-__logf(1.f + __expf(-z)))
                              : (z - __logf(1.f + __expf(z)));
        slam[t][j] = ls * (1.f / 16.f);
    }
    __syncthreads();

    // segmented cumsum along t
    int jj = tid & 63, seg = tid >> 6;
    float vals[16];
    {
        float run = 0.f;
#pragma unroll
        for (int i = 0; i < 16; i++) {
            run += slam[seg * 16 + i][jj];
            vals[i] = run;
        }
        stot[seg][jj] = run;
    }
    for (int e = tid; e < CHK * HVD; e += 256) {
        int t = e >> 7, j = e & 127;
        sv[t][j] = g_qkvg[VOFF(r0 + t, h, j)];
    }
    __syncthreads();
    {
        float off = 0.f;
#pragma unroll
        for (int p = 0; p < 3; p++)
            if (p < seg) off += stot[p][jj];
#pragma unroll
        for (int i = 0; i < 16; i++)
            slam[seg * 16 + i][jj] = vals[i] + off;
        if (seg == 3) selaml[jj] = __expf(vals[15] + off);
    }
    __syncthreads();

    for (int e = tid; e < CHK * HKD; e += 256) {
        int t = e >> 6, j = e & 63;
        float lam = slam[t][j];
        float en = __expf(-lam);
        float ep = __expf(lam);
        size_t gq = QOFF(r0 + t, h, j), gkk = KOFF(r0 + t, h, j);
        float kv = g_qkvg[gkk];
        g_qkvg[gkk] = kv * en;
        g_qkvg[gq] = g_qkvg[gq] * ep;
        slam[t][j] = kv * en * selaml[j];
    }
    if (tid < HKD)
        g_dec[((size_t)(b * NH + h) * NCK + c) * HKD + tid] = selaml[tid];
    __syncthreads();

    // P = kd^T @ v  (64x128) with packed f32x2, store fp16
    int wid = tid >> 5, lane = tid & 31;
    int k0 = wid * 8, v0 = lane * 4;
    unsigned long long acc2[4][4];
#pragma unroll
    for (int p = 0; p < 4; p++)
#pragma unroll
        for (int j = 0; j < 4; j++) acc2[p][j] = 0ULL;

    for (int t = 0; t < CHK; t++) {
        float4 vv = *(float4*)&sv[t][v0];
        unsigned long long vd0 = packdup(vv.x), vd1 = packdup(vv.y);
        unsigned long long vd2 = packdup(vv.z), vd3 = packdup(vv.w);
        ulonglong2 K01 = *(ulonglong2*)&slam[t][k0];
        ulonglong2 K23 = *(ulonglong2*)&slam[t][k0 + 4];
        unsigned long long a2[4] = {K01.x, K01.y, K23.x, K23.y};
#pragma unroll
        for (int p = 0; p < 4; p++) {
            fma2(acc2[p][0], a2[p], vd0);
            fma2(acc2[p][1], a2[p], vd1);
            fma2(acc2[p][2], a2[p], vd2);
            fma2(acc2[p][3], a2[p], vd3);
        }
    }
    size_t pb = ((size_t)(b * NH + h) * NCK + c) * HKD * HVD;
#pragma unroll
    for (int p = 0; p < 4; p++) {
        float2 u0 = unpack2(acc2[p][0]);
        float2 u1 = unpack2(acc2[p][1]);
        float2 u2 = unpack2(acc2[p][2]);
        float2 u3 = unpack2(acc2[p][3]);
        ushort4 r0h, r1h;
        r0h.x = __half_as_ushort(__float2half(u0.x));
        r0h.y = __half_as_ushort(__float2half(u1.x));
        r0h.z = __half_as_ushort(__float2half(u2.x));
        r0h.w = __half_as_ushort(__float2half(u3.x));
        r1h.x = __half_as_ushort(__float2half(u0.y));
        r1h.y = __half_as_ushort(__float2half(u1.y));
        r1h.z = __half_as_ushort(__float2half(u2.y));
        r1h.w = __half_as_ushort(__float2half(u3.y));
        *(ushort4*)&g_P[pb + (size_t)(k0 + 2 * p) * HVD + v0] = r0h;
        *(ushort4*)&g_P[pb + (size_t)(k0 + 2 * p + 1) * HVD + v0] = r1h;
    }
}

// ---------------- chunk-state scan (fp16 I/O, fp32 accum, half2 lanes) --------
__global__ void state_scan()
{
    int g = blockIdx.x * 256 + threadIdx.x;   // BSZ*NH*HKD*HVD/2 = 32768 threads
    int bh = g >> 12;
    int kk = (g >> 6) & 63;
    int v2 = g & 63;                           // pair index over vv
    float h0 = 0.f, h1 = 0.f;
#pragma unroll 4
    for (int c = 0; c < NCK; c++) {
        size_t base = ((size_t)(bh * NCK + c) * HKD + kk) * HVD + v2 * 2;
        __half2 hp = __floats2half2_rn(h0, h1);
        *(__half2*)&g_hs[base] = hp;
        float dec = g_dec[(size_t)(bh * NCK + c) * HKD + kk];
        float2 pv = __half22float2(*(const __half2*)&g_P[base]);
        h0 = dec * h0 + pv.x;
        h1 = dec * h1 + pv.y;
    }
}

// ---------------- per-chunk output + LN + gate, packed f32x2, transposed smem -
#define CO_SMEM ((4352 + 4352 + 8192) * 4)   // 67584 B

__global__ __launch_bounds__(256, 3) void chunk_out()
{
    extern __shared__ __align__(16) float sm[];
    float* sqT  = sm;            // q~ transposed: sqT[k*68 + t]
    float* sAT  = sm + 4352;     // A transposed:  sAT[i*68 + t]
    float* sbuf = sm + 8704;     // v then h: sbuf[t*128 + j]
    float* k2T  = sbuf;          // k2 transposed (phase 1 only)
    int c = blockIdx.x, hh = blockIdx.y, b = blockIdx.z;
    int tid = threadIdx.x;
    int r0 = b * SEQ + c * CHK;

    for (int e = tid; e < CHK * HKD; e += 256) {
        int t = e >> 6, j = e & 63;
        sqT[j * 68 + t] = g_qkvg[QOFF(r0 + t, hh, j)];
        k2T[j * 68 + t] = g_qkvg[KOFF(r0 + t, hh, j)];
    }
    __syncthreads();

    {
        int t = tid >> 2, i0 = (tid & 3) * 16;
        unsigned long long a2[8];
#pragma unroll
        for (int m = 0; m < 8; m++) a2[m] = 0ULL;
        if (i0 <= t) {
            for (int k = 0; k < HKD; k++) {
                unsigned long long qd = packdup(sqT[k * 68 + t]);
                const float* kr = &k2T[k * 68 + i0];
                ulonglong2 P01 = *(const ulonglong2*)kr;
                ulonglong2 P23 = *(const ulonglong2*)(kr + 4);
                ulonglong2 P45 = *(const ulonglong2*)(kr + 8);
                ulonglong2 P67 = *(const ulonglong2*)(kr + 12);
                fma2(a2[0], P01.x, qd); fma2(a2[1], P01.y, qd);
                fma2(a2[2], P23.x, qd); fma2(a2[3], P23.y, qd);
                fma2(a2[4], P45.x, qd); fma2(a2[5], P45.y, qd);
                fma2(a2[6], P67.x, qd); fma2(a2[7], P67.y, qd);
            }
        }
#pragma unroll
        for (int m = 0; m < 8; m++) {
            float2 u = unpack2(a2[m]);
            int ia = i0 + 2 * m, ib = ia + 1;
            sAT[ia * 68 + t] = (ia <= t) ? u.x : 0.f;
            sAT[ib * 68 + t] = (ib <= t) ? u.y : 0.f;
        }
    }
    __syncthreads();

    for (int e = tid; e < CHK * HVD; e += 256) {
        int t = e >> 7, j = e & 127;
        sbuf[t * 128 + j] = g_qkvg[VOFF(r0 + t, hh, j)];
    }
    __syncthreads();

    int wid = tid >> 5, lane = tid & 31;
    int t0 = wid * 8, v0 = lane * 4;
    unsigned long long acc2[4][4];
#pragma unroll
    for (int p = 0; p < 4; p++)
#pragma unroll
        for (int j = 0; j < 4; j++) acc2[p][j] = 0ULL;

    for (int i = 0; i < CHK; i++) {
        ulonglong2 A01 = *(ulonglong2*)&sAT[i * 68 + t0];
        ulonglong2 A23 = *(ulonglong2*)&sAT[i * 68 + t0 + 4];
        unsigned long long ap[4] = {A01.x, A01.y, A23.x, A23.y};
        float4 vv = *(float4*)&sbuf[i * 128 + v0];
        unsigned long long vd0 = packdup(vv.x), vd1 = packdup(vv.y);
        unsigned long long vd2 = packdup(vv.z), vd3 = packdup(vv.w);
#pragma unroll
        for (int p = 0; p < 4; p++) {
            fma2(acc2[p][0], ap[p], vd0);
            fma2(acc2[p][1], ap[p], vd1);
            fma2(acc2[p][2], ap[p], vd2);
            fma2(acc2[p][3], ap[p], vd3);
        }
    }
    __syncthreads();

    // load h_chunk (fp16 -> fp32)
    size_t hb = ((size_t)(b * NH + hh) * NCK + c) * HKD * HVD;
    for (int e = tid; e < HKD * HVD / 2; e += 256) {
        float2 hv = __half22float2(*(const __half2*)&g_hs[hb + e * 2]);
        sbuf[e * 2] = hv.x;
        sbuf[e * 2 + 1] = hv.y;
    }
    __syncthreads();

    for (int k = 0; k < HKD; k++) {
        ulonglong2 Q01 = *(ulonglong2*)&sqT[k * 68 + t0];
        ulonglong2 Q23 = *(ulonglong2*)&sqT[k * 68 + t0 + 4];
        unsigned long long qp[4] = {Q01.x, Q01.y, Q23.x, Q23.y};
        float4 hv = *(float4*)&sbuf[k * 128 + v0];
        unsigned long long hd0 = packdup(hv.x), hd1 = packdup(hv.y);
        unsigned long long hd2 = packdup(hv.z), hd3 = packdup(hv.w);
#pragma unroll
        for (int p = 0; p < 4; p++) {
            fma2(acc2[p][0], qp[p], hd0);
            fma2(acc2[p][1], qp[p], hd1);
            fma2(acc2[p][2], qp[p], hd2);
            fma2(acc2[p][3], qp[p], hd3);
        }
    }

#pragma unroll
    for (int p = 0; p < 4; p++) {
        float2 u0 = unpack2(acc2[p][0]);
        float2 u1 = unpack2(acc2[p][1]);
        float2 u2 = unpack2(acc2[p][2]);
        float2 u3 = unpack2(acc2[p][3]);
        float rowv[2][4] = {{u0.x, u1.x, u2.x, u3.x}, {u0.y, u1.y, u2.y, u3.y}};
#pragma unroll
        for (int rr = 0; rr < 2; rr++) {
            int t = t0 + 2 * p + rr;
            float ox = rowv[rr][0], oy = rowv[rr][1], oz = rowv[rr][2], ow = rowv[rr][3];
            float s = ox + oy + oz + ow;
#pragma unroll
            for (int off = 16; off; off >>= 1) s += __shfl_xor_sync(0xffffffffu, s, off);
            float mu = s * (1.f / HVD);
            float dx = ox - mu, dy = oy - mu, dz = oz - mu, dw = ow - mu;
            float ss = dx * dx + dy * dy + dz * dz + dw * dw;
#pragma unroll
            for (int off = 16; off; off >>= 1) ss += __shfl_xor_sync(0xffffffffu, ss, off);
            float inv = rsqrtf(ss * (1.f / HVD) + 1e-5f);
            float4 g4 = *(const float4*)&g_qkvg[GOFF(r0 + t, hh, v0)];
            float4 yv;
            yv.x = dx * inv * (g4.x / (1.f + __expf(-g4.x)));
            yv.y = dy * inv * (g4.y / (1.f + __expf(-g4.y)));
            yv.z = dz * inv * (g4.z / (1.f + __expf(-g4.z)));
            yv.w = dw * inv * (g4.w / (1.f + __expf(-g4.w)));
            ushort4 hsv, lsv;
            split2h(yv.x, hsv.x, lsv.x); split2h(yv.y, hsv.y, lsv.y);
            split2h(yv.z, hsv.z, lsv.z); split2h(yv.w, hsv.w, lsv.w);
            size_t yo = (size_t)(r0 + t) * DVD + hh * HVD + v0;
            *(ushort4*)&g_yh[yo] = hsv;
            *(ushort4*)&g_yl[yo] = lsv;
        }
    }
}

// ---------------- launch ----------------
extern "C" void kernel_launch(void* const* d_in, const int* in_sizes, int n_in,
                              void* d_out, int out_size)
{
    const float* x    = (const float*)d_in[0];
    const float* Wq   = (const float*)d_in[1];
    const float* Wk   = (const float*)d_in[2];
    const float* Wv   = (const float*)d_in[3];
    const float* Wg   = (const float*)d_in[4];
    const float* Wgk1 = (const float*)d_in[5];
    const float* Wgk2 = (const float*)d_in[6];
    const float* bgk2 = (const float*)d_in[7];
    const float* Wo   = (const float*)d_in[8];
    float* out = (float*)d_out;

    float* qkvg;
    __half *xh, *xl, *yh, *yl, *wh, *woh;
    cudaGetSymbolAddress((void**)&qkvg, g_qkvg);
    cudaGetSymbolAddress((void**)&xh, g_xh);
    cudaGetSymbolAddress((void**)&xl, g_xl);
    cudaGetSymbolAddress((void**)&yh, g_yh);
    cudaGetSymbolAddress((void**)&yl, g_yl);
    cudaGetSymbolAddress((void**)&wh, g_wh);
    cudaGetSymbolAddress((void**)&woh, g_woh);

    cudaFuncSetAttribute(gemm_f16x2, cudaFuncAttributeMaxDynamicSharedMemorySize, GEMM_SMEM);
    cudaFuncSetAttribute(chunk_out, cudaFuncAttributeMaxDynamicSharedMemorySize, CO_SMEM);

    dim3 t256(256);
    split_gkl<<<TT / 64, t256>>>(x, Wgk1);
    split_w<<<(DM * NQKVG + DVD * DM + 255) / 256, t256>>>(Wq, Wk, Wv, Wg, Wo);
    gemm_f16x2<<<dim3(NQKVG / 128, TT / 128), t256, GEMM_SMEM>>>(xh, xl, wh, qkvg,
                                                                 TT, NQKVG, DM, 256);
    chunk_prep<<<dim3(NCK, NH, BSZ), t256>>>(Wgk2, bgk2);
    state_scan<<<BSZ * NH * HKD * HVD / 512, t256>>>();
    chunk_out<<<dim3(NCK, NH, BSZ), t256, CO_SMEM>>>();
    gemm_f16x2<<<dim3(DM / 128, TT / 128), t256, GEMM_SMEM>>>(yh, yl, woh, out,
                                                              TT, DM, DVD, 0);
}

// round 16
// speedup vs baseline: 1.2159x; 1.2159x over previous
#include <cuda_runtime.h>
#include <cuda_fp16.h>
#include <math.h>

// ---------------- problem constants ----------------
#define BSZ 2
#define SEQ 16384
#define DM  512
#define DKD 256
#define DVD 512
#define NH  4
#define HKD 64
#define HVD 128
#define CHK 64
#define NCK (SEQ/CHK)
#define TT  (BSZ*SEQ)
#define GLR 16
#define NQKVG 1536       // packed [q|k|v|g] output width

#define QOFF(row,h,j) ((size_t)(row)*NQKVG + (size_t)(h)*64 + (j))
#define KOFF(row,h,j) ((size_t)(row)*NQKVG + 256 + (size_t)(h)*64 + (j))
#define VOFF(row,h,j) ((size_t)(row)*NQKVG + 512 + (size_t)(h)*128 + (j))
#define GOFF(row,h,j) ((size_t)(row)*NQKVG + 1024 + (size_t)(h)*128 + (j))

// ---------------- device scratch ----------------
__device__ float   g_qkvg[(size_t)TT*NQKVG];
__device__ float   g_gkl [(size_t)TT*GLR];
__device__ __half  g_P   [(size_t)BSZ*NH*NCK*HKD*HVD];   // fp16 chunk kv summaries
__device__ float   g_dec [(size_t)BSZ*NH*NCK*HKD];
__device__ __half  g_hs  [(size_t)BSZ*NH*NCK*HKD*HVD];   // fp16 chunk-start states
__device__ __half  g_xh  [(size_t)TT*DM];
__device__ __half  g_yh  [(size_t)TT*DVD];
__device__ __half  g_wh  [(size_t)DM*NQKVG];   // [K,N] packed [Wq|Wk|Wv|Wg], fp16
__device__ __half  g_woh [(size_t)DVD*DM];     // [K,N], fp16

// ---------------- helpers ----------------
// packed f32x2 FMA (Blackwell): d += a*b elementwise on 2 packed floats
__device__ __forceinline__ void fma2(unsigned long long& d,
                                     unsigned long long a, unsigned long long b)
{
    asm("fma.rn.f32x2 %0, %1, %2, %0;" : "+l"(d) : "l"(a), "l"(b));
}
__device__ __forceinline__ unsigned long long packdup(float v)
{
    unsigned long long r;
    asm("mov.b64 %0, {%1, %1};" : "=l"(r) : "f"(v));
    return r;
}
__device__ __forceinline__ float2 unpack2(unsigned long long v)
{
    float lo, hi;
    asm("mov.b64 {%0, %1}, %2;" : "=f"(lo), "=f"(hi) : "l"(v));
    return make_float2(lo, hi);
}

// ---------------- convert x -> fp16 + gkl = x @ Wgk1 (one pass over x) --------
__global__ void split_gkl(const float* __restrict__ x, const float* __restrict__ W)
{
    __shared__ float w[DM * GLR];
    int tid = threadIdx.x;
    for (int i = tid; i < DM * GLR; i += 256) w[i] = W[i];
    __syncthreads();

    int row = blockIdx.x * 64 + (tid >> 2);
    int q = (tid & 3) * 4;
    float a0 = 0.f, a1 = 0.f, a2 = 0.f, a3 = 0.f;
    const float4* xr = (const float4*)(x + (size_t)row * DM);
#pragma unroll 4
    for (int k4 = 0; k4 < DM / 4; k4++) {
        float4 v = xr[k4];
        const float* wb = &w[k4 * 4 * GLR + q];
        a0 += v.x * wb[0] + v.y * wb[GLR] + v.z * wb[2 * GLR] + v.w * wb[3 * GLR];
        a1 += v.x * wb[1] + v.y * wb[GLR + 1] + v.z * wb[2 * GLR + 1] + v.w * wb[3 * GLR + 1];
        a2 += v.x * wb[2] + v.y * wb[GLR + 2] + v.z * wb[2 * GLR + 2] + v.w * wb[3 * GLR + 2];
        a3 += v.x * wb[3] + v.y * wb[GLR + 3] + v.z * wb[2 * GLR + 3] + v.w * wb[3 * GLR + 3];
    }
    *(float4*)&g_gkl[(size_t)row * GLR + q] = make_float4(a0, a1, a2, a3);

    size_t base = (size_t)blockIdx.x * 64 * (DM / 4);
    const float4* x4 = (const float4*)x;
    for (int i = tid; i < 64 * DM / 4; i += 256) {
        float4 v = x4[base + i];
        ushort4 h;
        h.x = __half_as_ushort(__float2half(v.x));
        h.y = __half_as_ushort(__float2half(v.y));
        h.z = __half_as_ushort(__float2half(v.z));
        h.w = __half_as_ushort(__float2half(v.w));
        *(ushort4*)&g_xh[(base + i) * 4] = h;
    }
}

// ---------------- pack weights to fp16 ([K,N] layout for mma.sync B) ----------
__global__ void split_w(const float* __restrict__ Wq, const float* __restrict__ Wk,
                        const float* __restrict__ Wv, const float* __restrict__ Wg,
                        const float* __restrict__ Wo)
{
    int idx = blockIdx.x * 256 + threadIdx.x;
    if (idx < DM * NQKVG) {
        int row = idx / NQKVG, col = idx % NQKVG;
        float v;
        if      (col < 256)  v = Wq[row * DKD + col];
        else if (col < 512)  v = Wk[row * DKD + col - 256];
        else if (col < 1024) v = Wv[row * DVD + col - 512];
        else                 v = Wg[row * DVD + col - 1024];
        g_wh[idx] = __float2half(v);
    } else {
        int j = idx - DM * NQKVG;
        if (j < DVD * DM) g_woh[j] = __float2half(Wo[j]);
    }
}

// ---------------- fp16 tensor-core GEMM: C = A @ B -----------------------------
// 128x128 tile, BK=32, 256 threads, 2-stage cp.async.
#define GSTG 2
#define SA_STRIDE 40
#define SB_STRIDE 136
#define SA_SZ (128 * SA_STRIDE)              // shorts
#define SB_SZ (32 * SB_STRIDE)               // shorts
#define STG_SHORTS (SA_SZ + SB_SZ)           // A | B
#define GEMM_SMEM (GSTG * STG_SHORTS * 2)    // bytes = 37888

__global__ __launch_bounds__(256, 2) void gemm_f16(
    const __half* __restrict__ A, const __half* __restrict__ B,
    float* __restrict__ C, int M, int N, int K, int qcols)
{
    extern __shared__ __align__(16) unsigned short smem_u[];

    int tid = threadIdx.x;
    int bm = blockIdx.y * 128, bn = blockIdx.x * 128;
    int warp = tid >> 5, lane = tid & 31;
    int wm = (warp & 1) * 64, wn = (warp >> 1) * 32;

    float c[4][4][4];
#pragma unroll
    for (int a = 0; a < 4; a++)
#pragma unroll
        for (int b = 0; b < 4; b++)
#pragma unroll
            for (int d = 0; d < 4; d++) c[a][b][d] = 0.f;

    int nk = K / 32;

    int arow[2], acol[2], brow[2], bcol[2];
#pragma unroll
    for (int i = 0; i < 2; i++) {
        int idx = tid * 2 + i;
        arow[i] = idx >> 2; acol[i] = (idx & 3) * 8;
        int idxb = tid + i * 256;
        brow[i] = idxb >> 4; bcol[i] = (idxb & 15) * 8;
    }

#define GEMM_ISSUE(S) do {                                                     \
        int kt_ = (S) * 32;                                                    \
        unsigned short* st_ = smem_u + ((S) & 1) * STG_SHORTS;                 \
        _Pragma("unroll")                                                      \
        for (int i_ = 0; i_ < 2; i_++) {                                       \
            size_t goa_ = (size_t)(bm + arow[i_]) * K + kt_ + acol[i_];        \
            unsigned soa_ = arow[i_] * SA_STRIDE + acol[i_];                   \
            asm volatile("cp.async.cg.shared.global [%0],[%1],16;\n" ::        \
                "r"((unsigned)__cvta_generic_to_shared(st_ + soa_)), "l"(A + goa_)); \
            size_t gob_ = (size_t)(kt_ + brow[i_]) * N + bn + bcol[i_];        \
            unsigned sob_ = brow[i_] * SB_STRIDE + bcol[i_];                   \
            asm volatile("cp.async.cg.shared.global [%0],[%1],16;\n" ::        \
                "r"((unsigned)__cvta_generic_to_shared(st_ + SA_SZ + sob_)), "l"(B + gob_)); \
        }                                                                      \
        asm volatile("cp.async.commit_group;\n");                              \
    } while (0)

    GEMM_ISSUE(0);

    for (int s = 0; s < nk; s++) {
        asm volatile("cp.async.wait_group 0;\n");
        __syncthreads();
        if (s + 1 < nk) GEMM_ISSUE(s + 1);

        unsigned short* st = smem_u + (s & 1) * STG_SHORTS;
        unsigned short* pA = st;
        unsigned short* pB = st + SA_SZ;

#pragma unroll
        for (int kc = 0; kc < 2; kc++) {
            unsigned af[4][4], bf[4][2];
            int acol16 = kc * 16 + (lane >> 4) * 8;
            int arow16 = lane & 15;
#pragma unroll
            for (int mt = 0; mt < 4; mt++) {
                unsigned addr = (unsigned)__cvta_generic_to_shared(
                    &pA[(wm + mt * 16 + arow16) * SA_STRIDE + acol16]);
                asm volatile("ldmatrix.sync.aligned.m8n8.x4.shared.b16 {%0,%1,%2,%3},[%4];"
                    : "=r"(af[mt][0]), "=r"(af[mt][1]), "=r"(af[mt][2]), "=r"(af[mt][3])
                    : "r"(addr));
            }
            int brow16 = kc * 16 + (lane & 15);
#pragma unroll
            for (int g = 0; g < 2; g++) {
                int colb = wn + g * 16 + (lane >> 4) * 8;
                unsigned r0, r1, r2, r3;
                unsigned addr = (unsigned)__cvta_generic_to_shared(
                    &pB[brow16 * SB_STRIDE + colb]);
                asm volatile("ldmatrix.sync.aligned.m8n8.x4.trans.shared.b16 {%0,%1,%2,%3},[%4];"
                    : "=r"(r0), "=r"(r1), "=r"(r2), "=r"(r3) : "r"(addr));
                bf[g * 2][0] = r0; bf[g * 2][1] = r1;
                bf[g * 2 + 1][0] = r2; bf[g * 2 + 1][1] = r3;
            }
#pragma unroll
            for (int mt = 0; mt < 4; mt++)
#pragma unroll
                for (int nt = 0; nt < 4; nt++)
                    asm volatile(
                        "mma.sync.aligned.m16n8k16.row.col.f32.f16.f16.f32 "
                        "{%0,%1,%2,%3},{%4,%5,%6,%7},{%8,%9},{%0,%1,%2,%3};"
                        : "+f"(c[mt][nt][0]), "+f"(c[mt][nt][1]),
                          "+f"(c[mt][nt][2]), "+f"(c[mt][nt][3])
                        : "r"(af[mt][0]), "r"(af[mt][1]),
                          "r"(af[mt][2]), "r"(af[mt][3]),
                          "r"(bf[nt][0]), "r"(bf[nt][1]));
        }
    }
#undef GEMM_ISSUE

#pragma unroll
    for (int mt = 0; mt < 4; mt++)
#pragma unroll
        for (int nt = 0; nt < 4; nt++) {
            int colg = bn + wn + nt * 8 + (lane & 3) * 2;
            float alpha = (colg < qcols) ? 0.125f : 1.0f;
            int row0 = bm + wm + mt * 16 + (lane >> 2);
            *(float2*)&C[(size_t)row0 * N + colg] =
                make_float2(c[mt][nt][0] * alpha, c[mt][nt][1] * alpha);
            *(float2*)&C[(size_t)(row0 + 8) * N + colg] =
                make_float2(c[mt][nt][2] * alpha, c[mt][nt][3] * alpha);
        }
}

// ---------------- per-chunk prep: gate + cumsum + q~, k2, P(fp16), dec --------
__global__ void chunk_prep(const float* __restrict__ Wgk2, const float* __restrict__ bgk2)
{
    __shared__ __align__(16) float slam[CHK][HKD];   // Lam, reused as kd
    __shared__ __align__(16) float sv[CHK][HVD];     // staging then v
    __shared__ float stot[4][HKD];
    __shared__ float selaml[HKD];
    int c = blockIdx.x, h = blockIdx.y, b = blockIdx.z;
    int tid = threadIdx.x;
    int r0 = b * SEQ + c * CHK;
    int cb = h * HKD;

    float* sgkl = &sv[0][0];
    float* sw2  = &sv[0][0] + 1024;
    float* sbp  = &sv[0][0] + 2048;

    for (int e = tid; e < CHK * GLR; e += 256)
        sgkl[e] = g_gkl[(size_t)(r0 + (e >> 4)) * GLR + (e & 15)];
    for (int e = tid; e < GLR * HKD; e += 256)
        sw2[e] = Wgk2[(e >> 6) * DKD + cb + (e & 63)];
    if (tid < HKD) sbp[tid] = bgk2[cb + tid];
    __syncthreads();

    for (int e = tid; e < CHK * HKD; e += 256) {
        int t = e >> 6, j = e & 63;
        float z = sbp[j];
#pragma unroll
        for (int i = 0; i < GLR; i++)
            z += sgkl[t * GLR + i] * sw2[i * HKD + j];
        float ls = (z >= 0.f) ? (-__logf(1.f + __expf(-z)))
                              : (z - __logf(1.f + __expf(z)));
        slam[t][j] = ls * (1.f / 16.f);
    }
    __syncthreads();

    // segmented cumsum along t
    int jj = tid & 63, seg = tid >> 6;
    float vals[16];
    {
        float run = 0.f;
#pragma unroll
        for (int i = 0; i < 16; i++) {
            run += slam[seg * 16 + i][jj];
            vals[i] = run;
        }
        stot[seg][jj] = run;
    }
    for (int e = tid; e < CHK * HVD; e += 256) {
        int t = e >> 7, j = e & 127;
        sv[t][j] = g_qkvg[VOFF(r0 + t, h, j)];
    }
    __syncthreads();
    {
        float off = 0.f;
#pragma unroll
        for (int p = 0; p < 3; p++)
            if (p < seg) off += stot[p][jj];
#pragma unroll
        for (int i = 0; i < 16; i++)
            slam[seg * 16 + i][jj] = vals[i] + off;
        if (seg == 3) selaml[jj] = __expf(vals[15] + off);
    }
    __syncthreads();

    for (int e = tid; e < CHK * HKD; e += 256) {
        int t = e >> 6, j = e & 63;
        float lam = slam[t][j];
        float en = __expf(-lam);
        float ep = __expf(lam);
        size_t gq = QOFF(r0 + t, h, j), gkk = KOFF(r0 + t, h, j);
        float kv = g_qkvg[gkk];
        g_qkvg[gkk] = kv * en;
        g_qkvg[gq] = g_qkvg[gq] * ep;
        slam[t][j] = kv * en * selaml[j];
    }
    if (tid < HKD)
        g_dec[((size_t)(b * NH + h) * NCK + c) * HKD + tid] = selaml[tid];
    __syncthreads();

    // P = kd^T @ v  (64x128) with packed f32x2, store fp16
    int wid = tid >> 5, lane = tid & 31;
    int k0 = wid * 8, v0 = lane * 4;
    unsigned long long acc2[4][4];
#pragma unroll
    for (int p = 0; p < 4; p++)
#pragma unroll
        for (int j = 0; j < 4; j++) acc2[p][j] = 0ULL;

    for (int t = 0; t < CHK; t++) {
        float4 vv = *(float4*)&sv[t][v0];
        unsigned long long vd0 = packdup(vv.x), vd1 = packdup(vv.y);
        unsigned long long vd2 = packdup(vv.z), vd3 = packdup(vv.w);
        ulonglong2 K01 = *(ulonglong2*)&slam[t][k0];
        ulonglong2 K23 = *(ulonglong2*)&slam[t][k0 + 4];
        unsigned long long a2[4] = {K01.x, K01.y, K23.x, K23.y};
#pragma unroll
        for (int p = 0; p < 4; p++) {
            fma2(acc2[p][0], a2[p], vd0);
            fma2(acc2[p][1], a2[p], vd1);
            fma2(acc2[p][2], a2[p], vd2);
            fma2(acc2[p][3], a2[p], vd3);
        }
    }
    size_t pb = ((size_t)(b * NH + h) * NCK + c) * HKD * HVD;
#pragma unroll
    for (int p = 0; p < 4; p++) {
        float2 u0 = unpack2(acc2[p][0]);
        float2 u1 = unpack2(acc2[p][1]);
        float2 u2 = unpack2(acc2[p][2]);
        float2 u3 = unpack2(acc2[p][3]);
        ushort4 r0h, r1h;
        r0h.x = __half_as_ushort(__float2half(u0.x));
        r0h.y = __half_as_ushort(__float2half(u1.x));
        r0h.z = __half_as_ushort(__float2half(u2.x));
        r0h.w = __half_as_ushort(__float2half(u3.x));
        r1h.x = __half_as_ushort(__float2half(u0.y));
        r1h.y = __half_as_ushort(__float2half(u1.y));
        r1h.z = __half_as_ushort(__float2half(u2.y));
        r1h.w = __half_as_ushort(__float2half(u3.y));
        *(ushort4*)&g_P[pb + (size_t)(k0 + 2 * p) * HVD + v0] = r0h;
        *(ushort4*)&g_P[pb + (size_t)(k0 + 2 * p + 1) * HVD + v0] = r1h;
    }
}

// ---------------- chunk-state scan (fp16 I/O, fp32 accum, half2 lanes) --------
__global__ void state_scan()
{
    int g = blockIdx.x * 256 + threadIdx.x;
    int bh = g >> 12;
    int kk = (g >> 6) & 63;
    int v2 = g & 63;
    float h0 = 0.f, h1 = 0.f;
#pragma unroll 4
    for (int c = 0; c < NCK; c++) {
        size_t base = ((size_t)(bh * NCK + c) * HKD + kk) * HVD + v2 * 2;
        __half2 hp = __floats2half2_rn(h0, h1);
        *(__half2*)&g_hs[base] = hp;
        float dec = g_dec[(size_t)(bh * NCK + c) * HKD + kk];
        float2 pv = __half22float2(*(const __half2*)&g_P[base]);
        h0 = dec * h0 + pv.x;
        h1 = dec * h1 + pv.y;
    }
}

// ---------------- per-chunk output + LN + gate, packed f32x2, transposed smem -
#define CO_SMEM ((4352 + 4352 + 8192) * 4)   // 67584 B

__global__ __launch_bounds__(256, 3) void chunk_out()
{
    extern __shared__ __align__(16) float sm[];
    float* sqT  = sm;            // q~ transposed: sqT[k*68 + t]
    float* sAT  = sm + 4352;     // A transposed:  sAT[i*68 + t]
    float* sbuf = sm + 8704;     // v then h: sbuf[t*128 + j]
    float* k2T  = sbuf;          // k2 transposed (phase 1 only)
    int c = blockIdx.x, hh = blockIdx.y, b = blockIdx.z;
    int tid = threadIdx.x;
    int r0 = b * SEQ + c * CHK;

    for (int e = tid; e < CHK * HKD; e += 256) {
        int t = e >> 6, j = e & 63;
        sqT[j * 68 + t] = g_qkvg[QOFF(r0 + t, hh, j)];
        k2T[j * 68 + t] = g_qkvg[KOFF(r0 + t, hh, j)];
    }
    __syncthreads();

    {
        int t = tid >> 2, i0 = (tid & 3) * 16;
        unsigned long long a2[8];
#pragma unroll
        for (int m = 0; m < 8; m++) a2[m] = 0ULL;
        if (i0 <= t) {
            for (int k = 0; k < HKD; k++) {
                unsigned long long qd = packdup(sqT[k * 68 + t]);
                const float* kr = &k2T[k * 68 + i0];
                ulonglong2 P01 = *(const ulonglong2*)kr;
                ulonglong2 P23 = *(const ulonglong2*)(kr + 4);
                ulonglong2 P45 = *(const ulonglong2*)(kr + 8);
                ulonglong2 P67 = *(const ulonglong2*)(kr + 12);
                fma2(a2[0], P01.x, qd); fma2(a2[1], P01.y, qd);
                fma2(a2[2], P23.x, qd); fma2(a2[3], P23.y, qd);
                fma2(a2[4], P45.x, qd); fma2(a2[5], P45.y, qd);
                fma2(a2[6], P67.x, qd); fma2(a2[7], P67.y, qd);
            }
        }
#pragma unroll
        for (int m = 0; m < 8; m++) {
            float2 u = unpack2(a2[m]);
            int ia = i0 + 2 * m, ib = ia + 1;
            sAT[ia * 68 + t] = (ia <= t) ? u.x : 0.f;
            sAT[ib * 68 + t] = (ib <= t) ? u.y : 0.f;
        }
    }
    __syncthreads();

    for (int e = tid; e < CHK * HVD; e += 256) {
        int t = e >> 7, j = e & 127;
        sbuf[t * 128 + j] = g_qkvg[VOFF(r0 + t, hh, j)];
    }
    __syncthreads();

    int wid = tid >> 5, lane = tid & 31;
    int t0 = wid * 8, v0 = lane * 4;
    unsigned long long acc2[4][4];
#pragma unroll
    for (int p = 0; p < 4; p++)
#pragma unroll
        for (int j = 0; j < 4; j++) acc2[p][j] = 0ULL;

    for (int i = 0; i < CHK; i++) {
        ulonglong2 A01 = *(ulonglong2*)&sAT[i * 68 + t0];
        ulonglong2 A23 = *(ulonglong2*)&sAT[i * 68 + t0 + 4];
        unsigned long long ap[4] = {A01.x, A01.y, A23.x, A23.y};
        float4 vv = *(float4*)&sbuf[i * 128 + v0];
        unsigned long long vd0 = packdup(vv.x), vd1 = packdup(vv.y);
        unsigned long long vd2 = packdup(vv.z), vd3 = packdup(vv.w);
#pragma unroll
        for (int p = 0; p < 4; p++) {
            fma2(acc2[p][0], ap[p], vd0);
            fma2(acc2[p][1], ap[p], vd1);
            fma2(acc2[p][2], ap[p], vd2);
            fma2(acc2[p][3], ap[p], vd3);
        }
    }
    __syncthreads();

    // load h_chunk (fp16 -> fp32)
    size_t hb = ((size_t)(b * NH + hh) * NCK + c) * HKD * HVD;
    for (int e = tid; e < HKD * HVD / 2; e += 256) {
        float2 hv = __half22float2(*(const __half2*)&g_hs[hb + e * 2]);
        sbuf[e * 2] = hv.x;
        sbuf[e * 2 + 1] = hv.y;
    }
    __syncthreads();

    for (int k = 0; k < HKD; k++) {
        ulonglong2 Q01 = *(ulonglong2*)&sqT[k * 68 + t0];
        ulonglong2 Q23 = *(ulonglong2*)&sqT[k * 68 + t0 + 4];
        unsigned long long qp[4] = {Q01.x, Q01.y, Q23.x, Q23.y};
        float4 hv = *(float4*)&sbuf[k * 128 + v0];
        unsigned long long hd0 = packdup(hv.x), hd1 = packdup(hv.y);
        unsigned long long hd2 = packdup(hv.z), hd3 = packdup(hv.w);
#pragma unroll
        for (int p = 0; p < 4; p++) {
            fma2(acc2[p][0], qp[p], hd0);
            fma2(acc2[p][1], qp[p], hd1);
            fma2(acc2[p][2], qp[p], hd2);
            fma2(acc2[p][3], qp[p], hd3);
        }
    }

#pragma unroll
    for (int p = 0; p < 4; p++) {
        float2 u0 = unpack2(acc2[p][0]);
        float2 u1 = unpack2(acc2[p][1]);
        float2 u2 = unpack2(acc2[p][2]);
        float2 u3 = unpack2(acc2[p][3]);
        float rowv[2][4] = {{u0.x, u1.x, u2.x, u3.x}, {u0.y, u1.y, u2.y, u3.y}};
#pragma unroll
        for (int rr = 0; rr < 2; rr++) {
            int t = t0 + 2 * p + rr;
            float ox = rowv[rr][0], oy = rowv[rr][1], oz = rowv[rr][2], ow = rowv[rr][3];
            float s = ox + oy + oz + ow;
#pragma unroll
            for (int off = 16; off; off >>= 1) s += __shfl_xor_sync(0xffffffffu, s, off);
            float mu = s * (1.f / HVD);
            float dx = ox - mu, dy = oy - mu, dz = oz - mu, dw = ow - mu;
            float ss = dx * dx + dy * dy + dz * dz + dw * dw;
#pragma unroll
            for (int off = 16; off; off >>= 1) ss += __shfl_xor_sync(0xffffffffu, ss, off);
            float inv = rsqrtf(ss * (1.f / HVD) + 1e-5f);
            float4 g4 = *(const float4*)&g_qkvg[GOFF(r0 + t, hh, v0)];
            float4 yv;
            yv.x = dx * inv * (g4.x / (1.f + __expf(-g4.x)));
            yv.y = dy * inv * (g4.y / (1.f + __expf(-g4.y)));
            yv.z = dz * inv * (g4.z / (1.f + __expf(-g4.z)));
            yv.w = dw * inv * (g4.w / (1.f + __expf(-g4.w)));
            ushort4 hsv;
            hsv.x = __half_as_ushort(__float2half(yv.x));
            hsv.y = __half_as_ushort(__float2half(yv.y));
            hsv.z = __half_as_ushort(__float2half(yv.z));
            hsv.w = __half_as_ushort(__float2half(yv.w));
            size_t yo = (size_t)(r0 + t) * DVD + hh * HVD + v0;
            *(ushort4*)&g_yh[yo] = hsv;
        }
    }
}

// ---------------- launch ----------------
extern "C" void kernel_launch(void* const* d_in, const int* in_sizes, int n_in,
                              void* d_out, int out_size)
{
    const float* x    = (const float*)d_in[0];
    const float* Wq   = (const float*)d_in[1];
    const float* Wk   = (const float*)d_in[2];
    const float* Wv   = (const float*)d_in[3];
    const float* Wg   = (const float*)d_in[4];
    const float* Wgk1 = (const float*)d_in[5];
    const float* Wgk2 = (const float*)d_in[6];
    const float* bgk2 = (const float*)d_in[7];
    const float* Wo   = (const float*)d_in[8];
    float* out = (float*)d_out;

    float* qkvg;
    __half *xh, *yh, *wh, *woh;
    cudaGetSymbolAddress((void**)&qkvg, g_qkvg);
    cudaGetSymbolAddress((void**)&xh, g_xh);
    cudaGetSymbolAddress((void**)&yh, g_yh);
    cudaGetSymbolAddress((void**)&wh, g_wh);
    cudaGetSymbolAddress((void**)&woh, g_woh);

    cudaFuncSetAttribute(gemm_f16, cudaFuncAttributeMaxDynamicSharedMemorySize, GEMM_SMEM);
    cudaFuncSetAttribute(chunk_out, cudaFuncAttributeMaxDynamicSharedMemorySize, CO_SMEM);

    dim3 t256(256);
    split_gkl<<<TT / 64, t256>>>(x, Wgk1);
    split_w<<<(DM * NQKVG + DVD * DM + 255) / 256, t256>>>(Wq, Wk, Wv, Wg, Wo);
    gemm_f16<<<dim3(NQKVG / 128, TT / 128), t256, GEMM_SMEM>>>(xh, wh, qkvg,
                                                               TT, NQKVG, DM, 256);
    chunk_prep<<<dim3(NCK, NH, BSZ), t256>>>(Wgk2, bgk2);
    state_scan<<<BSZ * NH * HKD * HVD / 512, t256>>>();
    chunk_out<<<dim3(NCK, NH, BSZ), t256, CO_SMEM>>>();
    gemm_f16<<<dim3(DM / 128, TT / 128), t256, GEMM_SMEM>>>(yh, woh, out,
                                                            TT, DM, DVD, 0);
}